// round 4
// baseline (speedup 1.0000x reference)
#include <cuda_runtime.h>
#include <cstdint>
#include <cstddef>

#define BATCH 64
#define NSENT 1024
#define NENT  256
#define DIM   512
#define NEGV  (-1e9f)

// ---------------- scratch (device globals; no allocation allowed) ----------
__device__ float g_query[BATCH * DIM];
__device__ float g_qs[BATCH * DIM];
__device__ float g_qa[BATCH * DIM];
__device__ float g_ctx[BATCH * DIM];
__device__ float g_bias[BATCH * DIM];
__device__ float g_sidefeat[(size_t)BATCH * NENT * DIM];   // 33.5 MB
__device__ float g_escore_part[4 * BATCH * NENT];          // per n-tile partials
__device__ float g_score_part[4 * BATCH * NSENT];

// ---------------- helpers ---------------------------------------------------
__device__ __forceinline__ float sigmoidf_(float x) { return 1.f / (1.f + expf(-x)); }

__device__ __forceinline__ unsigned long long pack_dup(float x) {
    unsigned long long r;
    asm("mov.b64 %0, {%1, %1};" : "=l"(r) : "f"(x));
    return r;
}
__device__ __forceinline__ void fma2(unsigned long long& d,
                                     unsigned long long a,
                                     unsigned long long b) {
    asm("fma.rn.f32x2 %0, %1, %2, %0;" : "+l"(d) : "l"(a), "l"(b));
}
__device__ __forceinline__ void unpack2(float& lo, float& hi, unsigned long long v) {
    asm("mov.b64 {%0, %1}, %2;" : "=f"(lo), "=f"(hi) : "l"(v));
}

__device__ __forceinline__ float warp_sum(float v) {
    #pragma unroll
    for (int o = 16; o; o >>= 1) v += __shfl_xor_sync(0xffffffffu, v, o);
    return v;
}

// ---------------- K1: LSTM single step (h0=c0=0 -> f gate dead) -------------
__global__ void lstm_kernel(const float* __restrict__ x,
                            const float* __restrict__ wih,
                            const float* __restrict__ bih,
                            const float* __restrict__ bhh) {
    int b = blockIdx.x;
    __shared__ float xs[DIM];
    for (int i = threadIdx.x; i < DIM; i += blockDim.x) xs[i] = x[b * DIM + i];
    __syncthreads();
    int warp = threadIdx.x >> 5, lane = threadIdx.x & 31;
    for (int h = warp; h < DIM; h += 8) {
        const float* wi = wih + (size_t)h * DIM;
        const float* wg = wih + (size_t)(1024 + h) * DIM;
        const float* wo = wih + (size_t)(1536 + h) * DIM;
        float si = 0.f, sg = 0.f, so = 0.f;
        for (int d = lane * 4; d < DIM; d += 128) {
            float4 xv = *(const float4*)&xs[d];
            float4 a = *(const float4*)&wi[d];
            float4 g = *(const float4*)&wg[d];
            float4 o = *(const float4*)&wo[d];
            si += xv.x * a.x + xv.y * a.y + xv.z * a.z + xv.w * a.w;
            sg += xv.x * g.x + xv.y * g.y + xv.z * g.z + xv.w * g.w;
            so += xv.x * o.x + xv.y * o.y + xv.z * o.z + xv.w * o.w;
        }
        si = warp_sum(si); sg = warp_sum(sg); so = warp_sum(so);
        if (lane == 0) {
            si += bih[h] + bhh[h];
            sg += bih[1024 + h] + bhh[1024 + h];
            so += bih[1536 + h] + bhh[1536 + h];
            float c = sigmoidf_(si) * tanhf(sg);
            g_query[b * DIM + h] = sigmoidf_(so) * tanhf(c);
        }
    }
}

// ---------------- K2/K5: small projections  out[b,h] = src[b,:] @ W[:,h] (+add)
// mode 0: g_query @ W -> g_qs     mode 1: g_query @ W -> g_qa
// mode 2: g_ctx @ W + g_qa -> g_bias
__global__ void proj_kernel(const float* __restrict__ W, int mode) {
    int b = blockIdx.x;
    int h = threadIdx.x;  // 512 threads
    __shared__ float s[DIM];
    s[h] = (mode == 2) ? g_ctx[b * DIM + h] : g_query[b * DIM + h];
    __syncthreads();
    float acc = (mode == 2) ? g_qa[b * DIM + h] : 0.f;
    const float* Wp = W + h;
    #pragma unroll 8
    for (int d = 0; d < DIM; d++) acc = fmaf(s[d], Wp[(size_t)d * DIM], acc);
    float* out = (mode == 0) ? g_qs : (mode == 1) ? g_qa : g_bias;
    out[b * DIM + h] = acc;
}

// ---------------- K3/K6: fused GEMM + tanh-reduce ---------------------------
// MODE 0: A=entity_mem (R=NENT), W=side_wm, bias=g_qs, v=side_v,
//         store feat -> g_sidefeat, score partials -> g_escore_part
// MODE 1: A=sent_mem (R=NSENT),  W=attn_wm, bias=g_bias, v=attn_v,
//         score partials -> g_score_part
// Block tile 128(m) x 128(n), BK=8, 256 threads, 8x8 microtile via f32x2.
template <int MODE>
__global__ __launch_bounds__(256, 2)
void gemm_fused(const float* __restrict__ A, const float* __restrict__ W,
                const float* __restrict__ vvec) {
    constexpr int R = (MODE == 0) ? NENT : NSENT;
    __shared__ float As[2][8][128];
    __shared__ float Bs[2][8][128];

    int b  = blockIdx.z;
    int m0 = blockIdx.x * 128;
    int n0 = blockIdx.y * 128;
    const float* Ab = A + ((size_t)b * R + m0) * DIM;

    int tid = threadIdx.x;
    int tx = tid & 15, ty = tid >> 4;
    int lr = tid >> 1, lk = (tid & 1) * 4;        // A tile loaders
    int wk = tid >> 5, wn = (tid & 31) * 4;       // B tile loaders

    unsigned long long acc2[4][8];
    #pragma unroll
    for (int i = 0; i < 4; i++)
        #pragma unroll
        for (int j = 0; j < 8; j++) acc2[i][j] = 0ull;

    float4 ar = *(const float4*)(Ab + (size_t)lr * DIM + lk);
    float4 br = *(const float4*)(W + (size_t)wk * DIM + n0 + wn);
    As[0][lk + 0][lr] = ar.x; As[0][lk + 1][lr] = ar.y;
    As[0][lk + 2][lr] = ar.z; As[0][lk + 3][lr] = ar.w;
    *(float4*)&Bs[0][wk][wn] = br;
    __syncthreads();

    #pragma unroll 1
    for (int kt = 0; kt < 64; kt++) {
        int cur = kt & 1;
        if (kt < 63) {
            int k0 = (kt + 1) * 8;
            ar = *(const float4*)(Ab + (size_t)lr * DIM + k0 + lk);
            br = *(const float4*)(W + (size_t)(k0 + wk) * DIM + n0 + wn);
        }
        #pragma unroll
        for (int k = 0; k < 8; k++) {
            ulonglong2 aA = *(const ulonglong2*)&As[cur][k][ty * 8];
            ulonglong2 aB = *(const ulonglong2*)&As[cur][k][ty * 8 + 4];
            float4 b0 = *(const float4*)&Bs[cur][k][tx * 8];
            float4 b1 = *(const float4*)&Bs[cur][k][tx * 8 + 4];
            unsigned long long av[4] = {aA.x, aA.y, aB.x, aB.y};
            unsigned long long bd[8] = {
                pack_dup(b0.x), pack_dup(b0.y), pack_dup(b0.z), pack_dup(b0.w),
                pack_dup(b1.x), pack_dup(b1.y), pack_dup(b1.z), pack_dup(b1.w)};
            #pragma unroll
            for (int mp = 0; mp < 4; mp++)
                #pragma unroll
                for (int n = 0; n < 8; n++) fma2(acc2[mp][n], av[mp], bd[n]);
        }
        if (kt < 63) {
            int nx = (kt & 1) ^ 1;
            As[nx][lk + 0][lr] = ar.x; As[nx][lk + 1][lr] = ar.y;
            As[nx][lk + 2][lr] = ar.z; As[nx][lk + 3][lr] = ar.w;
            *(float4*)&Bs[nx][wk][wn] = br;
            __syncthreads();
        }
    }

    // ---- epilogue: tanh(feat + bias[n]) * v[n], reduce over n ----
    float accf[8][8];
    #pragma unroll
    for (int mp = 0; mp < 4; mp++)
        #pragma unroll
        for (int n = 0; n < 8; n++)
            unpack2(accf[2 * mp][n], accf[2 * mp + 1][n], acc2[mp][n]);

    const float* bv = (MODE == 0) ? &g_qs[b * DIM] : &g_bias[b * DIM];
    float bvr[8], vvr[8];
    #pragma unroll
    for (int n = 0; n < 8; n++) {
        int nn = n0 + tx * 8 + n;
        bvr[n] = bv[nn];
        vvr[n] = vvec[nn];
    }
    float* spart = (MODE == 0) ? g_escore_part : g_score_part;

    #pragma unroll
    for (int m = 0; m < 8; m++) {
        if (MODE == 0) {
            size_t off = ((size_t)b * R + m0 + ty * 8 + m) * DIM + n0 + tx * 8;
            float4 f0 = make_float4(accf[m][0], accf[m][1], accf[m][2], accf[m][3]);
            float4 f1 = make_float4(accf[m][4], accf[m][5], accf[m][6], accf[m][7]);
            *(float4*)&g_sidefeat[off]     = f0;
            *(float4*)&g_sidefeat[off + 4] = f1;
        }
        float s = 0.f;
        #pragma unroll
        for (int n = 0; n < 8; n++) s += tanhf(accf[m][n] + bvr[n]) * vvr[n];
        #pragma unroll
        for (int o = 8; o; o >>= 1) s += __shfl_down_sync(0xffffffffu, s, o, 16);
        if (tx == 0)
            spart[((size_t)blockIdx.y * BATCH + b) * R + m0 + ty * 8 + m] = s;
    }
}

// ---------------- K4: masked softmax over entities + ctx reduction ----------
__global__ void softmax_ctx_kernel(const int* __restrict__ entity_nums) {
    int b = blockIdx.x;
    int tid = threadIdx.x;  // 256 threads == NENT
    __shared__ float attn[NENT];
    __shared__ float red[8];

    int n = entity_nums[b];
    float v = g_escore_part[(0 * BATCH + b) * NENT + tid]
            + g_escore_part[(1 * BATCH + b) * NENT + tid]
            + g_escore_part[(2 * BATCH + b) * NENT + tid]
            + g_escore_part[(3 * BATCH + b) * NENT + tid];
    if (tid >= n) v = NEGV;

    // block max
    float m = v;
    #pragma unroll
    for (int o = 16; o; o >>= 1) m = fmaxf(m, __shfl_xor_sync(0xffffffffu, m, o));
    if ((tid & 31) == 0) red[tid >> 5] = m;
    __syncthreads();
    float M = red[0];
    #pragma unroll
    for (int i = 1; i < 8; i++) M = fmaxf(M, red[i]);
    __syncthreads();

    float e = expf(v - M);
    float s = warp_sum(e);
    if ((tid & 31) == 0) red[tid >> 5] = s;
    __syncthreads();
    float S = red[0];
    #pragma unroll
    for (int i = 1; i < 8; i++) S += red[i];
    attn[tid] = e / S;
    __syncthreads();

    // ctx[b,h] = sum_e attn[e] * side_feat[b,e,h]
    const float* fb = g_sidefeat + (size_t)b * NENT * DIM;
    for (int h = tid; h < DIM; h += 256) {
        float acc = 0.f;
        #pragma unroll 8
        for (int e2 = 0; e2 < NENT; e2++)
            acc = fmaf(attn[e2], fb[(size_t)e2 * DIM + h], acc);
        g_ctx[b * DIM + h] = acc;
    }
}

// ---------------- K7: finalize (sum partials + mask) ------------------------
__global__ void finalize_kernel(const int* __restrict__ sent_nums,
                                float* __restrict__ out) {
    int i = blockIdx.x * 256 + threadIdx.x;  // 65536 total
    int b = i >> 10, s = i & 1023;
    float v = g_score_part[(0 * BATCH + b) * NSENT + s]
            + g_score_part[(1 * BATCH + b) * NSENT + s]
            + g_score_part[(2 * BATCH + b) * NSENT + s]
            + g_score_part[(3 * BATCH + b) * NSENT + s];
    out[i] = (s < sent_nums[b]) ? v : NEGV;
}

// ---------------- launch -----------------------------------------------------
extern "C" void kernel_launch(void* const* d_in, const int* in_sizes, int n_in,
                              void* d_out, int out_size) {
    const float* sent_mem    = (const float*)d_in[0];
    const float* entity_mem  = (const float*)d_in[1];
    const float* ptr_in      = (const float*)d_in[2];
    const int*   sent_nums   = (const int*)d_in[3];
    const int*   entity_nums = (const int*)d_in[4];
    const float* lstm_w_ih   = (const float*)d_in[5];
    // d_in[6] = lstm_w_hh unused (h0 = 0)
    const float* lstm_b_ih   = (const float*)d_in[7];
    const float* lstm_b_hh   = (const float*)d_in[8];
    const float* attn_wm     = (const float*)d_in[9];
    const float* attn_wq     = (const float*)d_in[10];
    const float* attn_v      = (const float*)d_in[11];
    const float* side_wm     = (const float*)d_in[12];
    const float* side_wq     = (const float*)d_in[13];
    const float* side_v      = (const float*)d_in[14];
    const float* attn_ws     = (const float*)d_in[15];
    float* out = (float*)d_out;

    lstm_kernel<<<BATCH, 256>>>(ptr_in, lstm_w_ih, lstm_b_ih, lstm_b_hh);
    proj_kernel<<<BATCH, 512>>>(side_wq, 0);  // g_qs
    proj_kernel<<<BATCH, 512>>>(attn_wq, 1);  // g_qa
    gemm_fused<0><<<dim3(NENT / 128, 4, BATCH), 256>>>(entity_mem, side_wm, side_v);
    softmax_ctx_kernel<<<BATCH, 256>>>(entity_nums);
    proj_kernel<<<BATCH, 512>>>(attn_ws, 2);  // g_bias = g_qa + ctx@attn_ws
    gemm_fused<1><<<dim3(NSENT / 128, 4, BATCH), 256>>>(sent_mem, attn_wm, attn_v);
    finalize_kernel<<<BATCH * NSENT / 256, 256>>>(sent_nums, out);
}

// round 10
// speedup vs baseline: 2.4029x; 2.4029x over previous
#include <cuda_runtime.h>
#include <cuda_bf16.h>
#include <cstdint>
#include <cstddef>

#define BATCH 64
#define NSENT 1024
#define NENT  256
#define DIM   512
#define NEGV  (-1e9f)

// ---------------- device scratch --------------------------------------------
__device__ __align__(16) __nv_bfloat16 g_sent_bf[(size_t)BATCH * NSENT * DIM];
__device__ __align__(16) __nv_bfloat16 g_ent_bf[(size_t)BATCH * NENT * DIM];
__device__ __align__(16) __nv_bfloat16 g_wt[2][DIM * DIM];   // W^T: [n][k] bf16
__device__ float g_query[BATCH * DIM];
__device__ float g_qs[BATCH * DIM];
__device__ float g_qa[BATCH * DIM];
__device__ float g_ctx[BATCH * DIM];
__device__ float g_bias[BATCH * DIM];
__device__ float g_sidefeat[(size_t)BATCH * NENT * DIM];
__device__ float g_escore_part[4 * BATCH * NENT];
__device__ float g_score_part[4 * BATCH * NSENT];

// ---------------- helpers ----------------------------------------------------
__device__ __forceinline__ uint32_t smem_u32(const void* p) {
    uint32_t a;
    asm("{ .reg .u64 t; cvta.to.shared.u64 t, %1; cvt.u32.u64 %0, t; }" : "=r"(a) : "l"(p));
    return a;
}
__device__ __forceinline__ void cp16(uint32_t dst, const void* src) {
    asm volatile("cp.async.cg.shared.global [%0], [%1], 16;" :: "r"(dst), "l"(src));
}
__device__ __forceinline__ void ldm4(uint32_t* r, uint32_t a) {
    asm volatile("ldmatrix.sync.aligned.m8n8.x4.shared.b16 {%0,%1,%2,%3}, [%4];"
                 : "=r"(r[0]), "=r"(r[1]), "=r"(r[2]), "=r"(r[3]) : "r"(a));
}
__device__ __forceinline__ void ldm2(uint32_t* r, uint32_t a) {
    asm volatile("ldmatrix.sync.aligned.m8n8.x2.shared.b16 {%0,%1}, [%2];"
                 : "=r"(r[0]), "=r"(r[1]) : "r"(a));
}
__device__ __forceinline__ void mma16816(float* c, const uint32_t* a, const uint32_t* b) {
    asm volatile("mma.sync.aligned.m16n8k16.row.col.f32.bf16.bf16.f32 "
                 "{%0,%1,%2,%3}, {%4,%5,%6,%7}, {%8,%9}, {%0,%1,%2,%3};"
                 : "+f"(c[0]), "+f"(c[1]), "+f"(c[2]), "+f"(c[3])
                 : "r"(a[0]), "r"(a[1]), "r"(a[2]), "r"(a[3]), "r"(b[0]), "r"(b[1]));
}
__device__ __forceinline__ float tanh_fast(float x) {
    float e, r;
    asm("ex2.approx.f32 %0, %1;" : "=f"(e) : "f"(x * 2.8853900817779268f));  // e^(2x)
    asm("rcp.approx.f32 %0, %1;" : "=f"(r) : "f"(e + 1.f));
    return 1.f - 2.f * r;
}
__device__ __forceinline__ float sigmoidf_(float x) { return 1.f / (1.f + expf(-x)); }
__device__ __forceinline__ float warp_sum(float v) {
    #pragma unroll
    for (int o = 16; o; o >>= 1) v += __shfl_xor_sync(0xffffffffu, v, o);
    return v;
}

// ---------------- prepack: fp32 -> bf16 (grid-stride over float4) ------------
__global__ void cvt_bf16(const float4* __restrict__ src, __nv_bfloat162* __restrict__ dst) {
    int i = blockIdx.x * 256 + threadIdx.x;
    float4 v = src[i];
    dst[2 * i]     = __nv_bfloat162{__float2bfloat16(v.x), __float2bfloat16(v.y)};
    dst[2 * i + 1] = __nv_bfloat162{__float2bfloat16(v.z), __float2bfloat16(v.w)};
}

// ---------------- prepack W: W[k][n] fp32 -> Wt[n][k] bf16 -------------------
__global__ void prepack_w(const float* __restrict__ w0, const float* __restrict__ w1) {
    __shared__ float t[32][33];
    const float* src = blockIdx.z ? w1 : w0;
    __nv_bfloat16* dst = g_wt[blockIdx.z];
    int tx = threadIdx.x, ty = threadIdx.y;
    int k0 = blockIdx.x * 32, n0 = blockIdx.y * 32;
    t[ty][tx] = src[(size_t)(k0 + ty) * DIM + n0 + tx];
    __syncthreads();
    dst[(size_t)(n0 + ty) * DIM + k0 + tx] = __float2bfloat16(t[tx][ty]);
}

// ---------------- bf16 mma GEMM + fused tanh-reduce epilogue -----------------
// CTA: 128m x 128n, K=512 (BK=32, 2-stage cp.async). 8 warps: 2m x 4n, warp 64x32.
// MODE 0: A=g_ent_bf, W=g_wt[0], bias=g_qs  -> sidefeat + escore partials
// MODE 1: A=g_sent_bf, W=g_wt[1], bias=g_bias -> score partials
#define ASTR 80   // smem row stride bytes (32 bf16 = 64B data + 16B pad)
#define STG  10240
template <int MODE>
__global__ void __launch_bounds__(256, 2)
gemm_mma(const float* __restrict__ vvec) {
    constexpr int R = (MODE == 0) ? NENT : NSENT;
    __shared__ __align__(16) char sA[2 * STG];
    __shared__ __align__(16) char sB[2 * STG];
    __shared__ float bias_s[128], v_s[128];
    __shared__ float sPart[128][4];

    int tid = threadIdx.x, lane = tid & 31, wid = tid >> 5;
    int warp_m = wid >> 2, warp_n = wid & 3;
    int m0 = blockIdx.x * 128, n0 = blockIdx.y * 128, b = blockIdx.z;

    const __nv_bfloat16* Ab = (MODE == 0 ? g_ent_bf : g_sent_bf) + ((size_t)b * R + m0) * DIM;
    const __nv_bfloat16* Wt = g_wt[MODE] + (size_t)n0 * DIM;
    const float* bias = ((MODE == 0) ? g_qs : g_bias) + b * DIM + n0;

    if (tid < 128) { bias_s[tid] = bias[tid]; v_s[tid] = vvec[n0 + tid]; }

    const uint32_t sAu = smem_u32(sA), sBu = smem_u32(sB);
    // loader: thread handles 2 x 16B for A and 2 x 16B for B per stage
    int u0 = tid, u1 = tid + 256;
    int ar0 = u0 >> 2, as0 = u0 & 3, ar1 = u1 >> 2, as1 = u1 & 3;

    auto load_stage = [&](int kc, int st) {
        uint32_t da = sAu + st * STG, db = sBu + st * STG;
        const __nv_bfloat16* ak = Ab + kc * 32;
        const __nv_bfloat16* wk = Wt + kc * 32;
        cp16(da + ar0 * ASTR + as0 * 16, ak + (size_t)ar0 * DIM + as0 * 8);
        cp16(da + ar1 * ASTR + as1 * 16, ak + (size_t)ar1 * DIM + as1 * 8);
        cp16(db + ar0 * ASTR + as0 * 16, wk + (size_t)ar0 * DIM + as0 * 8);
        cp16(db + ar1 * ASTR + as1 * 16, wk + (size_t)ar1 * DIM + as1 * 8);
        asm volatile("cp.async.commit_group;" ::: "memory");
    };

    float c[4][4][4];
    #pragma unroll
    for (int i = 0; i < 4; i++)
        #pragma unroll
        for (int j = 0; j < 4; j++)
            #pragma unroll
            for (int q = 0; q < 4; q++) c[i][j][q] = 0.f;

    uint32_t aRow = sAu + (warp_m * 64 + (lane & 15)) * ASTR + (lane >> 4) * 16;
    uint32_t bRow = sBu + (warp_n * 32 + (lane & 7)) * ASTR + ((lane >> 3) & 1) * 16;

    load_stage(0, 0);
    #pragma unroll 1
    for (int kc = 0; kc < 16; kc++) {
        int cur = kc & 1;
        if (kc < 15) {
            load_stage(kc + 1, cur ^ 1);
            asm volatile("cp.async.wait_group 1;" ::: "memory");
        } else {
            asm volatile("cp.async.wait_group 0;" ::: "memory");
        }
        __syncthreads();
        uint32_t aBase = aRow + cur * STG, bBase = bRow + cur * STG;
        #pragma unroll
        for (int ks = 0; ks < 2; ks++) {
            uint32_t afr[4][4], bfr[4][2];
            #pragma unroll
            for (int mf = 0; mf < 4; mf++) ldm4(afr[mf], aBase + mf * 16 * ASTR + ks * 32);
            #pragma unroll
            for (int nf = 0; nf < 4; nf++) ldm2(bfr[nf], bBase + nf * 8 * ASTR + ks * 32);
            #pragma unroll
            for (int mf = 0; mf < 4; mf++)
                #pragma unroll
                for (int nf = 0; nf < 4; nf++) mma16816(c[mf][nf], afr[mf], bfr[nf]);
        }
        __syncthreads();
    }

    // ---- epilogue ----
    int qr = lane >> 2, qc = lane & 3;
    #pragma unroll
    for (int mf = 0; mf < 4; mf++) {
        int r0 = warp_m * 64 + mf * 16 + qr;    // CTA-local rows
        int r1 = r0 + 8;
        float s0 = 0.f, s1 = 0.f;
        #pragma unroll
        for (int nf = 0; nf < 4; nf++) {
            int nl = warp_n * 32 + nf * 8 + qc * 2;   // CTA-local n
            if (MODE == 0) {
                size_t base = ((size_t)b * NENT + m0) * DIM + n0 + nl;
                *(float2*)&g_sidefeat[base + (size_t)r0 * DIM] = make_float2(c[mf][nf][0], c[mf][nf][1]);
                *(float2*)&g_sidefeat[base + (size_t)r1 * DIM] = make_float2(c[mf][nf][2], c[mf][nf][3]);
            }
            s0 += tanh_fast(c[mf][nf][0] + bias_s[nl]) * v_s[nl]
                + tanh_fast(c[mf][nf][1] + bias_s[nl + 1]) * v_s[nl + 1];
            s1 += tanh_fast(c[mf][nf][2] + bias_s[nl]) * v_s[nl]
                + tanh_fast(c[mf][nf][3] + bias_s[nl + 1]) * v_s[nl + 1];
        }
        s0 += __shfl_xor_sync(0xffffffffu, s0, 1);
        s0 += __shfl_xor_sync(0xffffffffu, s0, 2);
        s1 += __shfl_xor_sync(0xffffffffu, s1, 1);
        s1 += __shfl_xor_sync(0xffffffffu, s1, 2);
        if (qc == 0) { sPart[r0][warp_n] = s0; sPart[r1][warp_n] = s1; }
    }
    __syncthreads();
    if (tid < 128) {
        float s = sPart[tid][0] + sPart[tid][1] + sPart[tid][2] + sPart[tid][3];
        float* spart = (MODE == 0) ? g_escore_part : g_score_part;
        spart[((size_t)blockIdx.y * BATCH + b) * R + m0 + tid] = s;
    }
}

// ---------------- LSTM single step (h0=c0=0 -> f gate dead) ------------------
__global__ void lstm_kernel(const float* __restrict__ x, const float* __restrict__ wih,
                            const float* __restrict__ bih, const float* __restrict__ bhh) {
    int b = blockIdx.x;
    __shared__ float xs[DIM];
    for (int i = threadIdx.x; i < DIM; i += blockDim.x) xs[i] = x[b * DIM + i];
    __syncthreads();
    int warp = threadIdx.x >> 5, lane = threadIdx.x & 31;
    for (int h = warp; h < DIM; h += 8) {
        const float* wi = wih + (size_t)h * DIM;
        const float* wg = wih + (size_t)(1024 + h) * DIM;
        const float* wo = wih + (size_t)(1536 + h) * DIM;
        float si = 0.f, sg = 0.f, so = 0.f;
        for (int d = lane * 4; d < DIM; d += 128) {
            float4 xv = *(const float4*)&xs[d];
            float4 a = *(const float4*)&wi[d];
            float4 g = *(const float4*)&wg[d];
            float4 o = *(const float4*)&wo[d];
            si += xv.x * a.x + xv.y * a.y + xv.z * a.z + xv.w * a.w;
            sg += xv.x * g.x + xv.y * g.y + xv.z * g.z + xv.w * g.w;
            so += xv.x * o.x + xv.y * o.y + xv.z * o.z + xv.w * o.w;
        }
        si = warp_sum(si); sg = warp_sum(sg); so = warp_sum(so);
        if (lane == 0) {
            si += bih[h] + bhh[h];
            sg += bih[1024 + h] + bhh[1024 + h];
            so += bih[1536 + h] + bhh[1536 + h];
            float cc = sigmoidf_(si) * tanhf(sg);
            g_query[b * DIM + h] = sigmoidf_(so) * tanhf(cc);
        }
    }
}

// ---------------- small projections ------------------------------------------
__global__ void proj_kernel(const float* __restrict__ W, int mode) {
    int b = blockIdx.x, h = threadIdx.x;
    __shared__ float s[DIM];
    s[h] = (mode == 2) ? g_ctx[b * DIM + h] : g_query[b * DIM + h];
    __syncthreads();
    float acc = (mode == 2) ? g_qa[b * DIM + h] : 0.f;
    const float* Wp = W + h;
    #pragma unroll 8
    for (int d = 0; d < DIM; d++) acc = fmaf(s[d], Wp[(size_t)d * DIM], acc);
    float* out = (mode == 0) ? g_qs : (mode == 1) ? g_qa : g_bias;
    out[b * DIM + h] = acc;
}

// ---------------- masked softmax over entities + ctx -------------------------
__global__ void softmax_ctx_kernel(const int* __restrict__ entity_nums) {
    int b = blockIdx.x, tid = threadIdx.x;   // 256 threads
    __shared__ float attn[NENT];
    __shared__ float red[8];
    int n = entity_nums[b];
    float v = g_escore_part[(0 * BATCH + b) * NENT + tid]
            + g_escore_part[(1 * BATCH + b) * NENT + tid]
            + g_escore_part[(2 * BATCH + b) * NENT + tid]
            + g_escore_part[(3 * BATCH + b) * NENT + tid];
    if (tid >= n) v = NEGV;
    float m = v;
    #pragma unroll
    for (int o = 16; o; o >>= 1) m = fmaxf(m, __shfl_xor_sync(0xffffffffu, m, o));
    if ((tid & 31) == 0) red[tid >> 5] = m;
    __syncthreads();
    float M = red[0];
    #pragma unroll
    for (int i = 1; i < 8; i++) M = fmaxf(M, red[i]);
    __syncthreads();
    float e = expf(v - M);
    float s = warp_sum(e);
    if ((tid & 31) == 0) red[tid >> 5] = s;
    __syncthreads();
    float S = red[0];
    #pragma unroll
    for (int i = 1; i < 8; i++) S += red[i];
    attn[tid] = e / S;
    __syncthreads();
    const float* fb = g_sidefeat + (size_t)b * NENT * DIM;
    for (int h = tid; h < DIM; h += 256) {
        float acc = 0.f;
        #pragma unroll 8
        for (int e2 = 0; e2 < NENT; e2++)
            acc = fmaf(attn[e2], fb[(size_t)e2 * DIM + h], acc);
        g_ctx[b * DIM + h] = acc;
    }
}

// ---------------- finalize (sum partials + mask) ------------------------------
__global__ void finalize_kernel(const int* __restrict__ sent_nums, float* __restrict__ out) {
    int i = blockIdx.x * 256 + threadIdx.x;
    int b = i >> 10, s = i & 1023;
    float v = g_score_part[(0 * BATCH + b) * NSENT + s]
            + g_score_part[(1 * BATCH + b) * NSENT + s]
            + g_score_part[(2 * BATCH + b) * NSENT + s]
            + g_score_part[(3 * BATCH + b) * NSENT + s];
    out[i] = (s < sent_nums[b]) ? v : NEGV;
}

// ---------------- launch ------------------------------------------------------
extern "C" void kernel_launch(void* const* d_in, const int* in_sizes, int n_in,
                              void* d_out, int out_size) {
    const float* sent_mem    = (const float*)d_in[0];
    const float* entity_mem  = (const float*)d_in[1];
    const float* ptr_in      = (const float*)d_in[2];
    const int*   sent_nums   = (const int*)d_in[3];
    const int*   entity_nums = (const int*)d_in[4];
    const float* lstm_w_ih   = (const float*)d_in[5];
    const float* lstm_b_ih   = (const float*)d_in[7];
    const float* lstm_b_hh   = (const float*)d_in[8];
    const float* attn_wm     = (const float*)d_in[9];
    const float* attn_wq     = (const float*)d_in[10];
    const float* attn_v      = (const float*)d_in[11];
    const float* side_wm     = (const float*)d_in[12];
    const float* side_wq     = (const float*)d_in[13];
    const float* side_v      = (const float*)d_in[14];
    const float* attn_ws     = (const float*)d_in[15];
    float* out = (float*)d_out;

    __nv_bfloat162* sent_dst;  cudaGetSymbolAddress((void**)&sent_dst, g_sent_bf);
    __nv_bfloat162* ent_dst;   cudaGetSymbolAddress((void**)&ent_dst, g_ent_bf);

    cvt_bf16<<<32768, 256>>>((const float4*)sent_mem, sent_dst);
    cvt_bf16<<<8192, 256>>>((const float4*)entity_mem, ent_dst);
    prepack_w<<<dim3(16, 16, 2), dim3(32, 32)>>>(side_wm, attn_wm);
    lstm_kernel<<<BATCH, 256>>>(ptr_in, lstm_w_ih, lstm_b_ih, lstm_b_hh);
    proj_kernel<<<BATCH, 512>>>(side_wq, 0);   // g_qs
    proj_kernel<<<BATCH, 512>>>(attn_wq, 1);   // g_qa
    gemm_mma<0><<<dim3(2, 4, BATCH), 256>>>(side_v);
    softmax_ctx_kernel<<<BATCH, 256>>>(entity_nums);
    proj_kernel<<<BATCH, 512>>>(attn_ws, 2);   // g_bias = g_qa + ctx@attn_ws
    gemm_mma<1><<<dim3(8, 4, BATCH), 256>>>(attn_v);
    finalize_kernel<<<BATCH * NSENT / 256, 256>>>(sent_nums, out);
}

// round 11
// speedup vs baseline: 4.2795x; 1.7809x over previous
#include <cuda_runtime.h>
#include <cuda_bf16.h>
#include <cstdint>
#include <cstddef>

#define BATCH 64
#define NSENT 1024
#define NENT  256
#define DIM   512
#define NEGV  (-1e9f)

// ---------------- device scratch --------------------------------------------
__device__ __align__(16) __nv_bfloat16 g_sent_bf[(size_t)BATCH * NSENT * DIM];
__device__ __align__(16) __nv_bfloat16 g_ent_bf[(size_t)BATCH * NENT * DIM];
__device__ __align__(16) __nv_bfloat16 g_wt[2][DIM * DIM];   // W^T: [n][k] bf16
__device__ __align__(16) float g_wqt[3][DIM * DIM];          // transposed fp32 wq/ws
__device__ float g_query[BATCH * DIM];
__device__ float g_qs[BATCH * DIM];
__device__ float g_qa[BATCH * DIM];
__device__ float g_ctx[BATCH * DIM];
__device__ float g_bias[BATCH * DIM];
__device__ float g_attn[BATCH * NENT];
__device__ float g_sidefeat[(size_t)BATCH * NENT * DIM];
__device__ float g_escore_part[4 * BATCH * NENT];
__device__ float g_score_part[4 * BATCH * NSENT];

// ---------------- helpers ----------------------------------------------------
__device__ __forceinline__ uint32_t smem_u32(const void* p) {
    uint32_t a;
    asm("{ .reg .u64 t; cvta.to.shared.u64 t, %1; cvt.u32.u64 %0, t; }" : "=r"(a) : "l"(p));
    return a;
}
__device__ __forceinline__ void cp16(uint32_t dst, const void* src) {
    asm volatile("cp.async.cg.shared.global [%0], [%1], 16;" :: "r"(dst), "l"(src));
}
__device__ __forceinline__ void ldm4(uint32_t* r, uint32_t a) {
    asm volatile("ldmatrix.sync.aligned.m8n8.x4.shared.b16 {%0,%1,%2,%3}, [%4];"
                 : "=r"(r[0]), "=r"(r[1]), "=r"(r[2]), "=r"(r[3]) : "r"(a));
}
__device__ __forceinline__ void ldm2(uint32_t* r, uint32_t a) {
    asm volatile("ldmatrix.sync.aligned.m8n8.x2.shared.b16 {%0,%1}, [%2];"
                 : "=r"(r[0]), "=r"(r[1]) : "r"(a));
}
__device__ __forceinline__ void mma16816(float* c, const uint32_t* a, const uint32_t* b) {
    asm volatile("mma.sync.aligned.m16n8k16.row.col.f32.bf16.bf16.f32 "
                 "{%0,%1,%2,%3}, {%4,%5,%6,%7}, {%8,%9}, {%0,%1,%2,%3};"
                 : "+f"(c[0]), "+f"(c[1]), "+f"(c[2]), "+f"(c[3])
                 : "r"(a[0]), "r"(a[1]), "r"(a[2]), "r"(a[3]), "r"(b[0]), "r"(b[1]));
}
__device__ __forceinline__ float tanh_fast(float x) {
    float e, r;
    asm("ex2.approx.f32 %0, %1;" : "=f"(e) : "f"(x * 2.8853900817779268f));  // e^(2x)
    asm("rcp.approx.f32 %0, %1;" : "=f"(r) : "f"(e + 1.f));
    return 1.f - 2.f * r;
}
__device__ __forceinline__ float sigmoidf_(float x) { return 1.f / (1.f + expf(-x)); }
__device__ __forceinline__ float warp_sum(float v) {
    #pragma unroll
    for (int o = 16; o; o >>= 1) v += __shfl_xor_sync(0xffffffffu, v, o);
    return v;
}
__device__ __forceinline__ float dot4(float4 a, float4 b) {
    return a.x * b.x + a.y * b.y + a.z * b.z + a.w * b.w;
}

// ---------------- prepack: fp32 -> bf16 (over float4) ------------------------
__global__ void cvt_bf16(const float4* __restrict__ src, __nv_bfloat162* __restrict__ dst) {
    int i = blockIdx.x * 256 + threadIdx.x;
    float4 v = src[i];
    dst[2 * i]     = __nv_bfloat162{__float2bfloat16(v.x), __float2bfloat16(v.y)};
    dst[2 * i + 1] = __nv_bfloat162{__float2bfloat16(v.z), __float2bfloat16(v.w)};
}

// ---------------- prepack W: W[k][n] fp32 -> Wt[n][k] bf16 -------------------
__global__ void prepack_w(const float* __restrict__ w0, const float* __restrict__ w1) {
    __shared__ float t[32][33];
    const float* src = blockIdx.z ? w1 : w0;
    __nv_bfloat16* dst = g_wt[blockIdx.z];
    int tx = threadIdx.x, ty = threadIdx.y;
    int k0 = blockIdx.x * 32, n0 = blockIdx.y * 32;
    t[ty][tx] = src[(size_t)(k0 + ty) * DIM + n0 + tx];
    __syncthreads();
    dst[(size_t)(n0 + ty) * DIM + k0 + tx] = __float2bfloat16(t[tx][ty]);
}

// ---------------- prepack small W^T fp32 (wq_side, wq_attn, ws) --------------
__global__ void prepack_wt(const float* __restrict__ w0, const float* __restrict__ w1,
                           const float* __restrict__ w2) {
    __shared__ float t[32][33];
    const float* src = (blockIdx.z == 0) ? w0 : (blockIdx.z == 1) ? w1 : w2;
    float* dst = g_wqt[blockIdx.z];
    int tx = threadIdx.x, ty = threadIdx.y;
    int k0 = blockIdx.x * 32, n0 = blockIdx.y * 32;
    t[ty][tx] = src[(size_t)(k0 + ty) * DIM + n0 + tx];
    __syncthreads();
    dst[(size_t)(n0 + ty) * DIM + k0 + tx] = t[tx][ty];
}

// ---------------- bf16 mma GEMM + fused tanh-reduce epilogue -----------------
#define ASTR 80
#define STG  10240
template <int MODE>
__global__ void __launch_bounds__(256, 2)
gemm_mma(const float* __restrict__ vvec) {
    constexpr int R = (MODE == 0) ? NENT : NSENT;
    __shared__ __align__(16) char sA[2 * STG];
    __shared__ __align__(16) char sB[2 * STG];
    __shared__ float bias_s[128], v_s[128];
    __shared__ float sPart[128][4];

    int tid = threadIdx.x, lane = tid & 31, wid = tid >> 5;
    int warp_m = wid >> 2, warp_n = wid & 3;
    int m0 = blockIdx.x * 128, n0 = blockIdx.y * 128, b = blockIdx.z;

    const __nv_bfloat16* Ab = (MODE == 0 ? g_ent_bf : g_sent_bf) + ((size_t)b * R + m0) * DIM;
    const __nv_bfloat16* Wt = g_wt[MODE] + (size_t)n0 * DIM;
    const float* bias = ((MODE == 0) ? g_qs : g_bias) + b * DIM + n0;

    if (tid < 128) { bias_s[tid] = bias[tid]; v_s[tid] = vvec[n0 + tid]; }

    const uint32_t sAu = smem_u32(sA), sBu = smem_u32(sB);
    int u0 = tid, u1 = tid + 256;
    int ar0 = u0 >> 2, as0 = u0 & 3, ar1 = u1 >> 2, as1 = u1 & 3;

    auto load_stage = [&](int kc, int st) {
        uint32_t da = sAu + st * STG, db = sBu + st * STG;
        const __nv_bfloat16* ak = Ab + kc * 32;
        const __nv_bfloat16* wk = Wt + kc * 32;
        cp16(da + ar0 * ASTR + as0 * 16, ak + (size_t)ar0 * DIM + as0 * 8);
        cp16(da + ar1 * ASTR + as1 * 16, ak + (size_t)ar1 * DIM + as1 * 8);
        cp16(db + ar0 * ASTR + as0 * 16, wk + (size_t)ar0 * DIM + as0 * 8);
        cp16(db + ar1 * ASTR + as1 * 16, wk + (size_t)ar1 * DIM + as1 * 8);
        asm volatile("cp.async.commit_group;" ::: "memory");
    };

    float c[4][4][4];
    #pragma unroll
    for (int i = 0; i < 4; i++)
        #pragma unroll
        for (int j = 0; j < 4; j++)
            #pragma unroll
            for (int q = 0; q < 4; q++) c[i][j][q] = 0.f;

    uint32_t aRow = sAu + (warp_m * 64 + (lane & 15)) * ASTR + (lane >> 4) * 16;
    uint32_t bRow = sBu + (warp_n * 32 + (lane & 7)) * ASTR + ((lane >> 3) & 1) * 16;

    load_stage(0, 0);
    #pragma unroll 1
    for (int kc = 0; kc < 16; kc++) {
        int cur = kc & 1;
        if (kc < 15) {
            load_stage(kc + 1, cur ^ 1);
            asm volatile("cp.async.wait_group 1;" ::: "memory");
        } else {
            asm volatile("cp.async.wait_group 0;" ::: "memory");
        }
        __syncthreads();
        uint32_t aBase = aRow + cur * STG, bBase = bRow + cur * STG;
        #pragma unroll
        for (int ks = 0; ks < 2; ks++) {
            uint32_t afr[4][4], bfr[4][2];
            #pragma unroll
            for (int mf = 0; mf < 4; mf++) ldm4(afr[mf], aBase + mf * 16 * ASTR + ks * 32);
            #pragma unroll
            for (int nf = 0; nf < 4; nf++) ldm2(bfr[nf], bBase + nf * 8 * ASTR + ks * 32);
            #pragma unroll
            for (int mf = 0; mf < 4; mf++)
                #pragma unroll
                for (int nf = 0; nf < 4; nf++) mma16816(c[mf][nf], afr[mf], bfr[nf]);
        }
        __syncthreads();
    }

    int qr = lane >> 2, qc = lane & 3;
    #pragma unroll
    for (int mf = 0; mf < 4; mf++) {
        int r0 = warp_m * 64 + mf * 16 + qr;
        int r1 = r0 + 8;
        float s0 = 0.f, s1 = 0.f;
        #pragma unroll
        for (int nf = 0; nf < 4; nf++) {
            int nl = warp_n * 32 + nf * 8 + qc * 2;
            if (MODE == 0) {
                size_t base = ((size_t)b * NENT + m0) * DIM + n0 + nl;
                *(float2*)&g_sidefeat[base + (size_t)r0 * DIM] = make_float2(c[mf][nf][0], c[mf][nf][1]);
                *(float2*)&g_sidefeat[base + (size_t)r1 * DIM] = make_float2(c[mf][nf][2], c[mf][nf][3]);
            }
            s0 += tanh_fast(c[mf][nf][0] + bias_s[nl]) * v_s[nl]
                + tanh_fast(c[mf][nf][1] + bias_s[nl + 1]) * v_s[nl + 1];
            s1 += tanh_fast(c[mf][nf][2] + bias_s[nl]) * v_s[nl]
                + tanh_fast(c[mf][nf][3] + bias_s[nl + 1]) * v_s[nl + 1];
        }
        s0 += __shfl_xor_sync(0xffffffffu, s0, 1);
        s0 += __shfl_xor_sync(0xffffffffu, s0, 2);
        s1 += __shfl_xor_sync(0xffffffffu, s1, 1);
        s1 += __shfl_xor_sync(0xffffffffu, s1, 2);
        if (qc == 0) { sPart[r0][warp_n] = s0; sPart[r1][warp_n] = s1; }
    }
    __syncthreads();
    if (tid < 128) {
        float s = sPart[tid][0] + sPart[tid][1] + sPart[tid][2] + sPart[tid][3];
        float* spart = (MODE == 0) ? g_escore_part : g_score_part;
        spart[((size_t)blockIdx.y * BATCH + b) * R + m0 + tid] = s;
    }
}

// ---------------- LSTM: warp-per-(b,h); grid (64, 64) x 256 ------------------
__global__ void lstm_kernel(const float* __restrict__ x, const float* __restrict__ wih,
                            const float* __restrict__ bih, const float* __restrict__ bhh) {
    int b = blockIdx.y;
    __shared__ float xs[DIM];
    xs[threadIdx.x] = x[b * DIM + threadIdx.x];
    xs[threadIdx.x + 256] = x[b * DIM + 256 + threadIdx.x];
    __syncthreads();
    int wid = threadIdx.x >> 5, lane = threadIdx.x & 31;
    int h = blockIdx.x * 8 + wid;
    const float* wi = wih + (size_t)h * DIM;
    const float* wg = wih + (size_t)(1024 + h) * DIM;
    const float* wo = wih + (size_t)(1536 + h) * DIM;
    float si = 0.f, sg = 0.f, so = 0.f;
    #pragma unroll
    for (int d = lane * 4; d < DIM; d += 128) {
        float4 xv = *(const float4*)&xs[d];
        si += dot4(xv, *(const float4*)&wi[d]);
        sg += dot4(xv, *(const float4*)&wg[d]);
        so += dot4(xv, *(const float4*)&wo[d]);
    }
    si = warp_sum(si); sg = warp_sum(sg); so = warp_sum(so);
    if (lane == 0) {
        si += bih[h] + bhh[h];
        sg += bih[1024 + h] + bhh[1024 + h];
        so += bih[1536 + h] + bhh[1536 + h];
        float cc = sigmoidf_(si) * tanhf(sg);
        g_query[b * DIM + h] = sigmoidf_(so) * tanhf(cc);
    }
}

// ---------------- proj: warp-per-(b,h) using transposed W --------------------
// mode 0: qs = query @ side_wq ; mode 1: qa = query @ attn_wq
// mode 2: bias = qa + ctx @ attn_ws
__global__ void proj_kernel(int mode) {
    int b = blockIdx.y;
    __shared__ float s[DIM];
    const float* src = (mode == 2) ? g_ctx : g_query;
    s[threadIdx.x] = src[b * DIM + threadIdx.x];
    s[threadIdx.x + 256] = src[b * DIM + 256 + threadIdx.x];
    __syncthreads();
    int wid = threadIdx.x >> 5, lane = threadIdx.x & 31;
    int h = blockIdx.x * 8 + wid;
    const float* wt = g_wqt[mode] + (size_t)h * DIM;
    float acc = 0.f;
    #pragma unroll
    for (int d = lane * 4; d < DIM; d += 128)
        acc += dot4(*(const float4*)&s[d], *(const float4*)&wt[d]);
    acc = warp_sum(acc);
    if (lane == 0) {
        if (mode == 0)      g_qs[b * DIM + h] = acc;
        else if (mode == 1) g_qa[b * DIM + h] = acc;
        else                g_bias[b * DIM + h] = g_qa[b * DIM + h] + acc;
    }
}

// ---------------- masked softmax over entities -> g_attn ---------------------
__global__ void softmax_kernel(const int* __restrict__ entity_nums) {
    int b = blockIdx.x, tid = threadIdx.x;   // 256 threads
    __shared__ float red[8];
    int n = entity_nums[b];
    float v = g_escore_part[(0 * BATCH + b) * NENT + tid]
            + g_escore_part[(1 * BATCH + b) * NENT + tid]
            + g_escore_part[(2 * BATCH + b) * NENT + tid]
            + g_escore_part[(3 * BATCH + b) * NENT + tid];
    if (tid >= n) v = NEGV;
    float m = v;
    #pragma unroll
    for (int o = 16; o; o >>= 1) m = fmaxf(m, __shfl_xor_sync(0xffffffffu, m, o));
    if ((tid & 31) == 0) red[tid >> 5] = m;
    __syncthreads();
    float M = red[0];
    #pragma unroll
    for (int i = 1; i < 8; i++) M = fmaxf(M, red[i]);
    __syncthreads();
    float e = expf(v - M);
    float s = warp_sum(e);
    if ((tid & 31) == 0) red[tid >> 5] = s;
    __syncthreads();
    float S = red[0];
    #pragma unroll
    for (int i = 1; i < 8; i++) S += red[i];
    g_attn[b * NENT + tid] = e / S;
}

// ---------------- ctx: grid (4, 64) x 128 -----------------------------------
__global__ void ctx_kernel() {
    int b = blockIdx.y;
    int h = blockIdx.x * 128 + threadIdx.x;
    __shared__ float attn[NENT];
    attn[threadIdx.x] = g_attn[b * NENT + threadIdx.x];
    attn[threadIdx.x + 128] = g_attn[b * NENT + 128 + threadIdx.x];
    __syncthreads();
    const float* fb = g_sidefeat + (size_t)b * NENT * DIM + h;
    float acc = 0.f;
    #pragma unroll 8
    for (int e = 0; e < NENT; e++)
        acc = fmaf(attn[e], fb[(size_t)e * DIM], acc);
    g_ctx[b * DIM + h] = acc;
}

// ---------------- finalize ----------------------------------------------------
__global__ void finalize_kernel(const int* __restrict__ sent_nums, float* __restrict__ out) {
    int i = blockIdx.x * 256 + threadIdx.x;
    int b = i >> 10, s = i & 1023;
    float v = g_score_part[(0 * BATCH + b) * NSENT + s]
            + g_score_part[(1 * BATCH + b) * NSENT + s]
            + g_score_part[(2 * BATCH + b) * NSENT + s]
            + g_score_part[(3 * BATCH + b) * NSENT + s];
    out[i] = (s < sent_nums[b]) ? v : NEGV;
}

// ---------------- launch ------------------------------------------------------
extern "C" void kernel_launch(void* const* d_in, const int* in_sizes, int n_in,
                              void* d_out, int out_size) {
    const float* sent_mem    = (const float*)d_in[0];
    const float* entity_mem  = (const float*)d_in[1];
    const float* ptr_in      = (const float*)d_in[2];
    const int*   sent_nums   = (const int*)d_in[3];
    const int*   entity_nums = (const int*)d_in[4];
    const float* lstm_w_ih   = (const float*)d_in[5];
    const float* lstm_b_ih   = (const float*)d_in[7];
    const float* lstm_b_hh   = (const float*)d_in[8];
    const float* attn_wm     = (const float*)d_in[9];
    const float* attn_wq     = (const float*)d_in[10];
    const float* attn_v      = (const float*)d_in[11];
    const float* side_wm     = (const float*)d_in[12];
    const float* side_wq     = (const float*)d_in[13];
    const float* side_v      = (const float*)d_in[14];
    const float* attn_ws     = (const float*)d_in[15];
    float* out = (float*)d_out;

    __nv_bfloat162* sent_dst;  cudaGetSymbolAddress((void**)&sent_dst, g_sent_bf);
    __nv_bfloat162* ent_dst;   cudaGetSymbolAddress((void**)&ent_dst, g_ent_bf);

    cvt_bf16<<<8192, 256>>>((const float4*)entity_mem, ent_dst);
    cvt_bf16<<<32768, 256>>>((const float4*)sent_mem, sent_dst);
    prepack_w<<<dim3(16, 16, 2), dim3(32, 32)>>>(side_wm, attn_wm);
    prepack_wt<<<dim3(16, 16, 3), dim3(32, 32)>>>(side_wq, attn_wq, attn_ws);
    lstm_kernel<<<dim3(64, BATCH), 256>>>(ptr_in, lstm_w_ih, lstm_b_ih, lstm_b_hh);
    proj_kernel<<<dim3(64, BATCH), 256>>>(0);   // g_qs
    proj_kernel<<<dim3(64, BATCH), 256>>>(1);   // g_qa
    gemm_mma<0><<<dim3(2, 4, BATCH), 256>>>(side_v);
    softmax_kernel<<<BATCH, 256>>>(entity_nums);
    ctx_kernel<<<dim3(4, BATCH), 128>>>();
    proj_kernel<<<dim3(64, BATCH), 256>>>(2);   // g_bias = g_qa + ctx@attn_ws
    gemm_mma<1><<<dim3(8, 4, BATCH), 256>>>(attn_v);
    finalize_kernel<<<BATCH * NSENT / 256, 256>>>(sent_nums, out);
}

// round 12
// speedup vs baseline: 4.4086x; 1.0302x over previous
#include <cuda_runtime.h>
#include <cuda_bf16.h>
#include <cstdint>
#include <cstddef>

#define BATCH 64
#define NSENT 1024
#define NENT  256
#define DIM   512
#define NEGV  (-1e9f)

// ---------------- device scratch --------------------------------------------
__device__ __align__(16) __nv_bfloat16 g_wt[2][DIM * DIM];   // W^T: [n][k] bf16
__device__ __align__(16) float g_wqt[3][DIM * DIM];          // transposed fp32 wq/ws
__device__ float g_query[BATCH * DIM];
__device__ float g_qs[BATCH * DIM];
__device__ float g_qa[BATCH * DIM];
__device__ float g_ctx[BATCH * DIM];
__device__ float g_bias[BATCH * DIM];
__device__ float g_attn[BATCH * NENT];
__device__ __align__(16) __nv_bfloat162 g_sidefeat[(size_t)BATCH * NENT * DIM / 2];
__device__ float g_escore_part[4 * BATCH * NENT];
__device__ float g_score_part[4 * BATCH * NSENT];

// ---- dynamic SMEM layout for gemm (bytes) ----
#define ASTR   80
#define STG    10240            // bf16 tile: 128 rows x 80B
#define FSTR   144
#define FSTG   18432            // fp32 staging: 128 rows x 144B
#define SM_A   0                // 2 x STG
#define SM_B   20480            // 2 x STG
#define SM_F   40960            // 2 x FSTG
#define SM_BI  77824            // 128 floats
#define SM_V   78336            // 128 floats
#define SM_P   78848            // 128 x 4 floats
#define SM_TOT 80896

// ---------------- helpers ----------------------------------------------------
__device__ __forceinline__ uint32_t smem_u32(const void* p) {
    uint32_t a;
    asm("{ .reg .u64 t; cvta.to.shared.u64 t, %1; cvt.u32.u64 %0, t; }" : "=r"(a) : "l"(p));
    return a;
}
__device__ __forceinline__ void cp16(uint32_t dst, const void* src) {
    asm volatile("cp.async.cg.shared.global [%0], [%1], 16;" :: "r"(dst), "l"(src));
}
__device__ __forceinline__ void ldm4(uint32_t* r, uint32_t a) {
    asm volatile("ldmatrix.sync.aligned.m8n8.x4.shared.b16 {%0,%1,%2,%3}, [%4];"
                 : "=r"(r[0]), "=r"(r[1]), "=r"(r[2]), "=r"(r[3]) : "r"(a));
}
__device__ __forceinline__ void ldm2(uint32_t* r, uint32_t a) {
    asm volatile("ldmatrix.sync.aligned.m8n8.x2.shared.b16 {%0,%1}, [%2];"
                 : "=r"(r[0]), "=r"(r[1]) : "r"(a));
}
__device__ __forceinline__ void mma16816(float* c, const uint32_t* a, const uint32_t* b) {
    asm volatile("mma.sync.aligned.m16n8k16.row.col.f32.bf16.bf16.f32 "
                 "{%0,%1,%2,%3}, {%4,%5,%6,%7}, {%8,%9}, {%0,%1,%2,%3};"
                 : "+f"(c[0]), "+f"(c[1]), "+f"(c[2]), "+f"(c[3])
                 : "r"(a[0]), "r"(a[1]), "r"(a[2]), "r"(a[3]), "r"(b[0]), "r"(b[1]));
}
__device__ __forceinline__ float tanh_fast(float x) {
    float e, r;
    asm("ex2.approx.f32 %0, %1;" : "=f"(e) : "f"(x * 2.8853900817779268f));
    asm("rcp.approx.f32 %0, %1;" : "=f"(r) : "f"(e + 1.f));
    return 1.f - 2.f * r;
}
__device__ __forceinline__ float sigmoidf_(float x) { return 1.f / (1.f + expf(-x)); }
__device__ __forceinline__ float warp_sum(float v) {
    #pragma unroll
    for (int o = 16; o; o >>= 1) v += __shfl_xor_sync(0xffffffffu, v, o);
    return v;
}
__device__ __forceinline__ float dot4(float4 a, float4 b) {
    return a.x * b.x + a.y * b.y + a.z * b.z + a.w * b.w;
}
__device__ __forceinline__ __nv_bfloat162 bfp(float a, float b) {
    return __nv_bfloat162{__float2bfloat16(a), __float2bfloat16(b)};
}

// ---------------- prepack W: W[k][n] fp32 -> Wt[n][k] bf16 -------------------
__global__ void prepack_w(const float* __restrict__ w0, const float* __restrict__ w1) {
    __shared__ float t[32][33];
    const float* src = blockIdx.z ? w1 : w0;
    __nv_bfloat16* dst = g_wt[blockIdx.z];
    int tx = threadIdx.x, ty = threadIdx.y;
    int k0 = blockIdx.x * 32, n0 = blockIdx.y * 32;
    t[ty][tx] = src[(size_t)(k0 + ty) * DIM + n0 + tx];
    __syncthreads();
    dst[(size_t)(n0 + ty) * DIM + k0 + tx] = __float2bfloat16(t[tx][ty]);
}

// ---------------- prepack small W^T fp32 (wq_side, wq_attn, ws) --------------
__global__ void prepack_wt(const float* __restrict__ w0, const float* __restrict__ w1,
                           const float* __restrict__ w2) {
    __shared__ float t[32][33];
    const float* src = (blockIdx.z == 0) ? w0 : (blockIdx.z == 1) ? w1 : w2;
    float* dst = g_wqt[blockIdx.z];
    int tx = threadIdx.x, ty = threadIdx.y;
    int k0 = blockIdx.x * 32, n0 = blockIdx.y * 32;
    t[ty][tx] = src[(size_t)(k0 + ty) * DIM + n0 + tx];
    __syncthreads();
    dst[(size_t)(n0 + ty) * DIM + k0 + tx] = t[tx][ty];
}

// ---------------- bf16 mma GEMM, fused fp32->bf16 convert + tanh-reduce ------
// Grid: (n_tiles fastest, m_tiles, batch) so n-tile CTAs sharing A run
// concurrently -> A fetched once from DRAM, then L2 hits.
// MODE 0: A=entity_mem, W=g_wt[0], bias=g_qs  -> sidefeat(bf16) + escore parts
// MODE 1: A=sent_mem,   W=g_wt[1], bias=g_bias -> score parts
template <int MODE>
__global__ void __launch_bounds__(256, 2)
gemm_mma(const float* __restrict__ A, const float* __restrict__ vvec) {
    constexpr int R = (MODE == 0) ? NENT : NSENT;
    extern __shared__ __align__(16) char smem[];
    float* bias_s = (float*)(smem + SM_BI);
    float* v_s    = (float*)(smem + SM_V);
    float* sPart  = (float*)(smem + SM_P);

    int tid = threadIdx.x, lane = tid & 31, wid = tid >> 5;
    int warp_m = wid >> 2, warp_n = wid & 3;
    int n0 = blockIdx.x * 128, m0 = blockIdx.y * 128, b = blockIdx.z;

    const float* Ab = A + ((size_t)b * R + m0) * DIM;
    const __nv_bfloat16* Wt = g_wt[MODE] + (size_t)n0 * DIM;
    const float* bias = ((MODE == 0) ? g_qs : g_bias) + b * DIM + n0;

    if (tid < 128) { bias_s[tid] = bias[tid]; v_s[tid] = vvec[n0 + tid]; }

    const uint32_t sAu = smem_u32(smem + SM_A), sBu = smem_u32(smem + SM_B);
    const uint32_t sFu = smem_u32(smem + SM_F);
    int br0 = tid >> 2, bs0 = tid & 3, br1 = (tid + 256) >> 2, bs1 = (tid + 256) & 3;

    auto load_stage = [&](int kc, int st) {
        // A fp32: 128 rows x 128B -> staging (1024 x 16B units)
        uint32_t df = sFu + st * FSTG;
        const float* ak = Ab + kc * 32;
        #pragma unroll
        for (int i = 0; i < 4; i++) {
            int u = tid + i * 256, r = u >> 3, c = u & 7;
            cp16(df + r * FSTR + c * 16, ak + (size_t)r * DIM + c * 4);
        }
        // B bf16: 128 rows x 64B (512 x 16B units)
        uint32_t db = sBu + st * STG;
        const __nv_bfloat16* wk = Wt + kc * 32;
        cp16(db + br0 * ASTR + bs0 * 16, wk + (size_t)br0 * DIM + bs0 * 8);
        cp16(db + br1 * ASTR + bs1 * 16, wk + (size_t)br1 * DIM + bs1 * 8);
        asm volatile("cp.async.commit_group;" ::: "memory");
    };
    auto convert = [&](int st) {   // fp32 staging -> bf16 ldmatrix tile
        int r = tid >> 1, h = tid & 1;
        const char* sg = smem + SM_F + st * FSTG + r * FSTR + h * 64;
        float4 x0 = *(const float4*)(sg);
        float4 x1 = *(const float4*)(sg + 16);
        float4 x2 = *(const float4*)(sg + 32);
        float4 x3 = *(const float4*)(sg + 48);
        __nv_bfloat162 o[8] = {bfp(x0.x, x0.y), bfp(x0.z, x0.w), bfp(x1.x, x1.y), bfp(x1.z, x1.w),
                               bfp(x2.x, x2.y), bfp(x2.z, x2.w), bfp(x3.x, x3.y), bfp(x3.z, x3.w)};
        char* d = smem + SM_A + st * STG + r * ASTR + h * 32;
        *(uint4*)d = *(uint4*)&o[0];
        *(uint4*)(d + 16) = *(uint4*)&o[4];
    };

    float c[4][4][4];
    #pragma unroll
    for (int i = 0; i < 4; i++)
        #pragma unroll
        for (int j = 0; j < 4; j++)
            #pragma unroll
            for (int q = 0; q < 4; q++) c[i][j][q] = 0.f;

    uint32_t aRow = sAu + (warp_m * 64 + (lane & 15)) * ASTR + (lane >> 4) * 16;
    uint32_t bRow = sBu + (warp_n * 32 + (lane & 7)) * ASTR + ((lane >> 3) & 1) * 16;

    load_stage(0, 0);
    #pragma unroll 1
    for (int kc = 0; kc < 16; kc++) {
        int cur = kc & 1;
        if (kc < 15) {
            load_stage(kc + 1, cur ^ 1);
            asm volatile("cp.async.wait_group 1;" ::: "memory");
        } else {
            asm volatile("cp.async.wait_group 0;" ::: "memory");
        }
        __syncthreads();
        convert(cur);
        __syncthreads();
        uint32_t aBase = aRow + cur * STG, bBase = bRow + cur * STG;
        #pragma unroll
        for (int ks = 0; ks < 2; ks++) {
            uint32_t afr[4][4], bfr[4][2];
            #pragma unroll
            for (int mf = 0; mf < 4; mf++) ldm4(afr[mf], aBase + mf * 16 * ASTR + ks * 32);
            #pragma unroll
            for (int nf = 0; nf < 4; nf++) ldm2(bfr[nf], bBase + nf * 8 * ASTR + ks * 32);
            #pragma unroll
            for (int mf = 0; mf < 4; mf++)
                #pragma unroll
                for (int nf = 0; nf < 4; nf++) mma16816(c[mf][nf], afr[mf], bfr[nf]);
        }
        __syncthreads();
    }

    int qr = lane >> 2, qc = lane & 3;
    #pragma unroll
    for (int mf = 0; mf < 4; mf++) {
        int r0 = warp_m * 64 + mf * 16 + qr;
        int r1 = r0 + 8;
        float s0 = 0.f, s1 = 0.f;
        #pragma unroll
        for (int nf = 0; nf < 4; nf++) {
            int nl = warp_n * 32 + nf * 8 + qc * 2;
            if (MODE == 0) {
                size_t base = ((size_t)b * NENT + m0) * (DIM / 2) + (n0 + nl) / 2;
                g_sidefeat[base + (size_t)r0 * (DIM / 2)] = bfp(c[mf][nf][0], c[mf][nf][1]);
                g_sidefeat[base + (size_t)r1 * (DIM / 2)] = bfp(c[mf][nf][2], c[mf][nf][3]);
            }
            s0 += tanh_fast(c[mf][nf][0] + bias_s[nl]) * v_s[nl]
                + tanh_fast(c[mf][nf][1] + bias_s[nl + 1]) * v_s[nl + 1];
            s1 += tanh_fast(c[mf][nf][2] + bias_s[nl]) * v_s[nl]
                + tanh_fast(c[mf][nf][3] + bias_s[nl + 1]) * v_s[nl + 1];
        }
        s0 += __shfl_xor_sync(0xffffffffu, s0, 1);
        s0 += __shfl_xor_sync(0xffffffffu, s0, 2);
        s1 += __shfl_xor_sync(0xffffffffu, s1, 1);
        s1 += __shfl_xor_sync(0xffffffffu, s1, 2);
        if (qc == 0) { sPart[r0 * 4 + warp_n] = s0; sPart[r1 * 4 + warp_n] = s1; }
    }
    __syncthreads();
    if (tid < 128) {
        float s = sPart[tid * 4] + sPart[tid * 4 + 1] + sPart[tid * 4 + 2] + sPart[tid * 4 + 3];
        float* spart = (MODE == 0) ? g_escore_part : g_score_part;
        spart[((size_t)blockIdx.x * BATCH + b) * R + m0 + tid] = s;
    }
}

// ---------------- LSTM: warp-per-(b,h) ---------------------------------------
__global__ void lstm_kernel(const float* __restrict__ x, const float* __restrict__ wih,
                            const float* __restrict__ bih, const float* __restrict__ bhh) {
    int b = blockIdx.y;
    __shared__ float xs[DIM];
    xs[threadIdx.x] = x[b * DIM + threadIdx.x];
    xs[threadIdx.x + 256] = x[b * DIM + 256 + threadIdx.x];
    __syncthreads();
    int wid = threadIdx.x >> 5, lane = threadIdx.x & 31;
    int h = blockIdx.x * 8 + wid;
    const float* wi = wih + (size_t)h * DIM;
    const float* wg = wih + (size_t)(1024 + h) * DIM;
    const float* wo = wih + (size_t)(1536 + h) * DIM;
    float si = 0.f, sg = 0.f, so = 0.f;
    #pragma unroll
    for (int d = lane * 4; d < DIM; d += 128) {
        float4 xv = *(const float4*)&xs[d];
        si += dot4(xv, *(const float4*)&wi[d]);
        sg += dot4(xv, *(const float4*)&wg[d]);
        so += dot4(xv, *(const float4*)&wo[d]);
    }
    si = warp_sum(si); sg = warp_sum(sg); so = warp_sum(so);
    if (lane == 0) {
        si += bih[h] + bhh[h];
        sg += bih[1024 + h] + bhh[1024 + h];
        so += bih[1536 + h] + bhh[1536 + h];
        float cc = sigmoidf_(si) * tanhf(sg);
        g_query[b * DIM + h] = sigmoidf_(so) * tanhf(cc);
    }
}

// ---------------- proj01: qs and qa in one launch (z = which W) --------------
__global__ void proj01_kernel() {
    int b = blockIdx.y, mode = blockIdx.z;
    __shared__ float s[DIM];
    s[threadIdx.x] = g_query[b * DIM + threadIdx.x];
    s[threadIdx.x + 256] = g_query[b * DIM + 256 + threadIdx.x];
    __syncthreads();
    int wid = threadIdx.x >> 5, lane = threadIdx.x & 31;
    int h = blockIdx.x * 8 + wid;
    const float* wt = g_wqt[mode] + (size_t)h * DIM;
    float acc = 0.f;
    #pragma unroll
    for (int d = lane * 4; d < DIM; d += 128)
        acc += dot4(*(const float4*)&s[d], *(const float4*)&wt[d]);
    acc = warp_sum(acc);
    if (lane == 0) ((mode == 0) ? g_qs : g_qa)[b * DIM + h] = acc;
}

// ---------------- proj2: bias = qa + ctx @ ws --------------------------------
__global__ void proj2_kernel() {
    int b = blockIdx.y;
    __shared__ float s[DIM];
    s[threadIdx.x] = g_ctx[b * DIM + threadIdx.x];
    s[threadIdx.x + 256] = g_ctx[b * DIM + 256 + threadIdx.x];
    __syncthreads();
    int wid = threadIdx.x >> 5, lane = threadIdx.x & 31;
    int h = blockIdx.x * 8 + wid;
    const float* wt = g_wqt[2] + (size_t)h * DIM;
    float acc = 0.f;
    #pragma unroll
    for (int d = lane * 4; d < DIM; d += 128)
        acc += dot4(*(const float4*)&s[d], *(const float4*)&wt[d]);
    acc = warp_sum(acc);
    if (lane == 0) g_bias[b * DIM + h] = g_qa[b * DIM + h] + acc;
}

// ---------------- masked softmax over entities -> g_attn ---------------------
__global__ void softmax_kernel(const int* __restrict__ entity_nums) {
    int b = blockIdx.x, tid = threadIdx.x;
    __shared__ float red[8];
    int n = entity_nums[b];
    float v = g_escore_part[(0 * BATCH + b) * NENT + tid]
            + g_escore_part[(1 * BATCH + b) * NENT + tid]
            + g_escore_part[(2 * BATCH + b) * NENT + tid]
            + g_escore_part[(3 * BATCH + b) * NENT + tid];
    if (tid >= n) v = NEGV;
    float m = v;
    #pragma unroll
    for (int o = 16; o; o >>= 1) m = fmaxf(m, __shfl_xor_sync(0xffffffffu, m, o));
    if ((tid & 31) == 0) red[tid >> 5] = m;
    __syncthreads();
    float M = red[0];
    #pragma unroll
    for (int i = 1; i < 8; i++) M = fmaxf(M, red[i]);
    __syncthreads();
    float e = expf(v - M);
    float s = warp_sum(e);
    if ((tid & 31) == 0) red[tid >> 5] = s;
    __syncthreads();
    float S = red[0];
    #pragma unroll
    for (int i = 1; i < 8; i++) S += red[i];
    g_attn[b * NENT + tid] = e / S;
}

// ---------------- ctx from bf16 sidefeat: grid (2, 64) x 128 -----------------
__global__ void ctx_kernel() {
    int b = blockIdx.y;
    int h2 = blockIdx.x * 128 + threadIdx.x;   // bf162 column index (0..255)
    __shared__ float attn[NENT];
    attn[threadIdx.x] = g_attn[b * NENT + threadIdx.x];
    attn[threadIdx.x + 128] = g_attn[b * NENT + 128 + threadIdx.x];
    __syncthreads();
    const __nv_bfloat162* fb = g_sidefeat + (size_t)b * NENT * (DIM / 2) + h2;
    float a0 = 0.f, a1 = 0.f;
    #pragma unroll 8
    for (int e = 0; e < NENT; e++) {
        __nv_bfloat162 f = fb[(size_t)e * (DIM / 2)];
        a0 = fmaf(attn[e], __bfloat162float(f.x), a0);
        a1 = fmaf(attn[e], __bfloat162float(f.y), a1);
    }
    g_ctx[b * DIM + 2 * h2]     = a0;
    g_ctx[b * DIM + 2 * h2 + 1] = a1;
}

// ---------------- finalize ----------------------------------------------------
__global__ void finalize_kernel(const int* __restrict__ sent_nums, float* __restrict__ out) {
    int i = blockIdx.x * 256 + threadIdx.x;
    int b = i >> 10, s = i & 1023;
    float v = g_score_part[(0 * BATCH + b) * NSENT + s]
            + g_score_part[(1 * BATCH + b) * NSENT + s]
            + g_score_part[(2 * BATCH + b) * NSENT + s]
            + g_score_part[(3 * BATCH + b) * NSENT + s];
    out[i] = (s < sent_nums[b]) ? v : NEGV;
}

// ---------------- launch ------------------------------------------------------
extern "C" void kernel_launch(void* const* d_in, const int* in_sizes, int n_in,
                              void* d_out, int out_size) {
    const float* sent_mem    = (const float*)d_in[0];
    const float* entity_mem  = (const float*)d_in[1];
    const float* ptr_in      = (const float*)d_in[2];
    const int*   sent_nums   = (const int*)d_in[3];
    const int*   entity_nums = (const int*)d_in[4];
    const float* lstm_w_ih   = (const float*)d_in[5];
    const float* lstm_b_ih   = (const float*)d_in[7];
    const float* lstm_b_hh   = (const float*)d_in[8];
    const float* attn_wm     = (const float*)d_in[9];
    const float* attn_wq     = (const float*)d_in[10];
    const float* attn_v      = (const float*)d_in[11];
    const float* side_wm     = (const float*)d_in[12];
    const float* side_wq     = (const float*)d_in[13];
    const float* side_v      = (const float*)d_in[14];
    const float* attn_ws     = (const float*)d_in[15];
    float* out = (float*)d_out;

    static bool attr_done = false;
    if (!attr_done) {
        cudaFuncSetAttribute(gemm_mma<0>, cudaFuncAttributeMaxDynamicSharedMemorySize, SM_TOT);
        cudaFuncSetAttribute(gemm_mma<1>, cudaFuncAttributeMaxDynamicSharedMemorySize, SM_TOT);
        attr_done = true;
    }

    prepack_w<<<dim3(16, 16, 2), dim3(32, 32)>>>(side_wm, attn_wm);
    prepack_wt<<<dim3(16, 16, 3), dim3(32, 32)>>>(side_wq, attn_wq, attn_ws);
    lstm_kernel<<<dim3(64, BATCH), 256>>>(ptr_in, lstm_w_ih, lstm_b_ih, lstm_b_hh);
    proj01_kernel<<<dim3(64, BATCH, 2), 256>>>();
    gemm_mma<0><<<dim3(4, 2, BATCH), 256, SM_TOT>>>(entity_mem, side_v);
    softmax_kernel<<<BATCH, 256>>>(entity_nums);
    ctx_kernel<<<dim3(2, BATCH), 128>>>();
    proj2_kernel<<<dim3(64, BATCH), 256>>>();
    gemm_mma<1><<<dim3(4, 8, BATCH), 256, SM_TOT>>>(sent_mem, attn_v);
    finalize_kernel<<<BATCH * NSENT / 256, 256>>>(sent_nums, out);
}